// round 5
// baseline (speedup 1.0000x reference)
#include <cuda_runtime.h>
#include <cuda_bf16.h>

// EdgeModel: out = relu(concat(src,dest,edge_attr,u[batch]) @ W1 + b1) @ W2 + b2
// E=500000, F_IN=35, H=512, OUT=512. Fully fused, fp32 FFMA baseline.
// NOTE: batch is int32 (JAX downgrades int64 without x64 mode).

#define BM 64            // edges per CTA
#define NTHREADS 256
#define NODE_F 9
#define U_F 16
#define F_IN 35          // 9 + 9 + 1 + 16
#define HDIM 512
#define OUTF 512
#define KT 32            // k-tile rows for weight staging

// smem layout (floats):
//   xs : [BM][36]        (padded 35->36)
//   hs : [BM][516]       (padded 512->516, keeps 16B alignment)
//   ws : [KT][512]       (weight k-tile)
#define XS_STRIDE 36
#define HS_STRIDE 516
#define SMEM_FLOATS (BM*XS_STRIDE + BM*HS_STRIDE + KT*512)

__global__ __launch_bounds__(NTHREADS, 1)
void edge_mlp_fused(const float* __restrict__ src,
                    const float* __restrict__ dest,
                    const float* __restrict__ edge_attr,
                    const float* __restrict__ u,
                    const int* __restrict__ batch,
                    const float* __restrict__ W1,
                    const float* __restrict__ b1,
                    const float* __restrict__ W2,
                    const float* __restrict__ b2,
                    float* __restrict__ out,
                    int E, int n_graphs)
{
    extern __shared__ float smem[];
    float* xs = smem;                       // [BM][36]
    float* hs = xs + BM * XS_STRIDE;        // [BM][516]
    float* ws = hs + BM * HS_STRIDE;        // [KT][512]

    const int tid = threadIdx.x;
    const int tn  = tid & 31;               // n-block 0..31 (4 cols per group, 4 groups)
    const int tm  = tid >> 5;               // m-block 0..7  (rows tm + 8*i)
    const int e0  = blockIdx.x * BM;

    // ---------------- gather x = [src | dest | edge_attr | u[batch]] ----------------
    for (int idx = tid; idx < BM * F_IN; idx += NTHREADS) {
        int m = idx / F_IN;
        int f = idx - m * F_IN;
        int e = e0 + m;
        float v = 0.0f;
        if (e < E) {
            if (f < NODE_F)            v = src[(long)e * NODE_F + f];
            else if (f < 2 * NODE_F)   v = dest[(long)e * NODE_F + (f - NODE_F)];
            else if (f == 2 * NODE_F)  v = edge_attr[e];
            else {
                int g = batch[e];
                g = (g < 0) ? 0 : (g >= n_graphs ? n_graphs - 1 : g);  // defensive clamp
                v = u[(long)g * U_F + (f - 2 * NODE_F - 1)];
            }
        }
        xs[m * XS_STRIDE + f] = v;
    }
    __syncthreads();

    // ---------------- GEMM1: h = relu(x @ W1 + b1), h -> smem ----------------
    float acc[8][16];
    {
        // init with b1
        #pragma unroll
        for (int g = 0; g < 4; g++) {
            float4 bb = *(const float4*)&b1[tn * 4 + g * 128];
            #pragma unroll
            for (int i = 0; i < 8; i++) {
                acc[i][g*4+0] = bb.x; acc[i][g*4+1] = bb.y;
                acc[i][g*4+2] = bb.z; acc[i][g*4+3] = bb.w;
            }
        }

        #pragma unroll
        for (int kt = 0; kt < 2; kt++) {
            const int k0 = kt * KT;
            const int nrows = (k0 + KT <= F_IN) ? KT : (F_IN - k0);   // 32 then 3
            // stage W1 tile
            for (int p = tid; p < nrows * 128; p += NTHREADS) {
                int r = p >> 7, c4 = p & 127;
                *(float4*)&ws[r * 512 + c4 * 4] =
                    *(const float4*)&W1[(long)(k0 + r) * 512 + c4 * 4];
            }
            __syncthreads();

            for (int k = 0; k < nrows; k++) {
                float xv[8];
                #pragma unroll
                for (int i = 0; i < 8; i++)
                    xv[i] = xs[(tm + 8*i) * XS_STRIDE + k0 + k];
                #pragma unroll
                for (int g = 0; g < 4; g++) {
                    float4 w4 = *(const float4*)&ws[k * 512 + tn * 4 + g * 128];
                    #pragma unroll
                    for (int i = 0; i < 8; i++) {
                        acc[i][g*4+0] = fmaf(xv[i], w4.x, acc[i][g*4+0]);
                        acc[i][g*4+1] = fmaf(xv[i], w4.y, acc[i][g*4+1]);
                        acc[i][g*4+2] = fmaf(xv[i], w4.z, acc[i][g*4+2]);
                        acc[i][g*4+3] = fmaf(xv[i], w4.w, acc[i][g*4+3]);
                    }
                }
            }
            __syncthreads();
        }

        // relu + store h to smem
        #pragma unroll
        for (int i = 0; i < 8; i++) {
            #pragma unroll
            for (int g = 0; g < 4; g++) {
                float4 hv;
                hv.x = fmaxf(acc[i][g*4+0], 0.0f);
                hv.y = fmaxf(acc[i][g*4+1], 0.0f);
                hv.z = fmaxf(acc[i][g*4+2], 0.0f);
                hv.w = fmaxf(acc[i][g*4+3], 0.0f);
                *(float4*)&hs[(tm + 8*i) * HS_STRIDE + tn * 4 + g * 128] = hv;
            }
        }
        __syncthreads();
    }

    // ---------------- GEMM2: out = h @ W2 + b2 ----------------
    #pragma unroll
    for (int g = 0; g < 4; g++) {
        float4 bb = *(const float4*)&b2[tn * 4 + g * 128];
        #pragma unroll
        for (int i = 0; i < 8; i++) {
            acc[i][g*4+0] = bb.x; acc[i][g*4+1] = bb.y;
            acc[i][g*4+2] = bb.z; acc[i][g*4+3] = bb.w;
        }
    }

    for (int kt = 0; kt < HDIM / KT; kt++) {          // 16 k-tiles
        const int k0 = kt * KT;
        // stage W2 tile [KT][512]
        #pragma unroll 4
        for (int p = tid; p < KT * 128; p += NTHREADS) {
            int r = p >> 7, c4 = p & 127;
            *(float4*)&ws[r * 512 + c4 * 4] =
                *(const float4*)&W2[(long)(k0 + r) * 512 + c4 * 4];
        }
        __syncthreads();

        #pragma unroll
        for (int k4 = 0; k4 < KT / 4; k4++) {
            const int k = k4 * 4;
            float4 hv[8];
            #pragma unroll
            for (int i = 0; i < 8; i++)
                hv[i] = *(const float4*)&hs[(tm + 8*i) * HS_STRIDE + k0 + k];
            #pragma unroll
            for (int kk = 0; kk < 4; kk++) {
                float4 w4[4];
                #pragma unroll
                for (int g = 0; g < 4; g++)
                    w4[g] = *(const float4*)&ws[(k + kk) * 512 + tn * 4 + g * 128];
                #pragma unroll
                for (int i = 0; i < 8; i++) {
                    float hval = (kk == 0) ? hv[i].x : (kk == 1) ? hv[i].y
                               : (kk == 2) ? hv[i].z : hv[i].w;
                    #pragma unroll
                    for (int g = 0; g < 4; g++) {
                        acc[i][g*4+0] = fmaf(hval, w4[g].x, acc[i][g*4+0]);
                        acc[i][g*4+1] = fmaf(hval, w4[g].y, acc[i][g*4+1]);
                        acc[i][g*4+2] = fmaf(hval, w4[g].z, acc[i][g*4+2]);
                        acc[i][g*4+3] = fmaf(hval, w4[g].w, acc[i][g*4+3]);
                    }
                }
            }
        }
        __syncthreads();
    }

    // ---------------- store out ----------------
    #pragma unroll
    for (int i = 0; i < 8; i++) {
        const int e = e0 + tm + 8*i;
        if (e < E) {
            #pragma unroll
            for (int g = 0; g < 4; g++) {
                float4 ov;
                ov.x = acc[i][g*4+0]; ov.y = acc[i][g*4+1];
                ov.z = acc[i][g*4+2]; ov.w = acc[i][g*4+3];
                *(float4*)&out[(long)e * OUTF + tn * 4 + g * 128] = ov;
            }
        }
    }
}

extern "C" void kernel_launch(void* const* d_in, const int* in_sizes, int n_in,
                              void* d_out, int out_size) {
    const float* src       = (const float*)d_in[0];
    const float* dest      = (const float*)d_in[1];
    const float* edge_attr = (const float*)d_in[2];
    const float* u         = (const float*)d_in[3];
    const int*   batch     = (const int*)d_in[4];     // int32 (JAX default, no x64)
    const float* W1        = (const float*)d_in[5];
    const float* b1        = (const float*)d_in[6];
    const float* W2        = (const float*)d_in[7];
    const float* b2        = (const float*)d_in[8];
    float*       out       = (float*)d_out;

    const int E        = in_sizes[0] / NODE_F;   // src is [E, 9]
    const int n_graphs = in_sizes[3] / U_F;      // u is [n_graphs, 16]
    const int smem_bytes = SMEM_FLOATS * (int)sizeof(float);

    static int configured = 0;
    if (!configured) {
        cudaFuncSetAttribute(edge_mlp_fused,
                             cudaFuncAttributeMaxDynamicSharedMemorySize, smem_bytes);
        configured = 1;
    }

    const int grid = (E + BM - 1) / BM;
    edge_mlp_fused<<<grid, NTHREADS, smem_bytes>>>(
        src, dest, edge_attr, u, batch, W1, b1, W2, b2, out, E, n_graphs);
}

// round 13
// speedup vs baseline: 1.9006x; 1.9006x over previous
#include <cuda_runtime.h>
#include <cuda_bf16.h>
#include <cstdint>

// EdgeModel: out = relu(concat(src,dest,edge_attr,u[batch]) @ W1 + b1) @ W2 + b2
// E=500000, F_IN=35, H=512, OUT=512.
// Fused kernel: gather + GEMM1 (FFMA) + GEMM2 (mma.sync bf16x3, fp32 accum).
// Round 10 fix: GEMM2 k-loop covered only 8*32=256 of 512 k-elements (rel_err
// 0.697 = sqrt(0.5) signature). kt loop now 16 tiles; wait/prefetch adjusted.

#define NODE_F 9
#define U_F 16
#define F_IN 35
#define HDIM 512
#define OUTF 512
#define BM 64
#define NT 256

#define NKT (HDIM / 32)           // 16 k-tiles of 32

// ---------------- smem byte layout ----------------
#define HS_STRIDE_B 1040
#define HS_HI_OFF 0
#define HS_LO_OFF 66560
#define R3_OFF    133120
#define XS_OFF    R3_OFF
#define WS_OFF    (R3_OFF + 9216)
#define BS_STRIDE_B 80            // 40 bf16 per row (32 data + 8 pad)
#define BTILE_BYTES 20480         // 256 rows * 80 B (one of hi/lo)
#define BBUF_OFF(i) (R3_OFF + (i) * (2 * BTILE_BYTES))   // [hi | lo]
#define SMEM_TOTAL (R3_OFF + 2 * 2 * BTILE_BYTES)        // 215040 B

// ---------------- global scratch: pre-split W2^T (bf16 hi/lo, [n][k]) ----------------
__device__ __align__(16) __nv_bfloat16 g_w2t_hi[HDIM * OUTF];
__device__ __align__(16) __nv_bfloat16 g_w2t_lo[HDIM * OUTF];

// ---------------- PTX helpers (all baseline sm_80+ features) ----------------
__device__ __forceinline__ uint32_t smem_u32(const void* p) {
    uint32_t a;
    asm("{ .reg .u64 t; cvta.to.shared.u64 t, %1; cvt.u32.u64 %0, t; }" : "=r"(a) : "l"(p));
    return a;
}
__device__ __forceinline__ void ldsm_x4(uint32_t addr, uint32_t* r) {
    asm volatile("ldmatrix.sync.aligned.m8n8.x4.shared.b16 {%0,%1,%2,%3}, [%4];"
                 : "=r"(r[0]), "=r"(r[1]), "=r"(r[2]), "=r"(r[3]) : "r"(addr));
}
__device__ __forceinline__ void mma_bf16(float* d, const uint32_t* a, const uint32_t* b) {
    asm volatile(
        "mma.sync.aligned.m16n8k16.row.col.f32.bf16.bf16.f32 "
        "{%0,%1,%2,%3}, {%4,%5,%6,%7}, {%8,%9}, {%0,%1,%2,%3};"
        : "+f"(d[0]), "+f"(d[1]), "+f"(d[2]), "+f"(d[3])
        : "r"(a[0]), "r"(a[1]), "r"(a[2]), "r"(a[3]), "r"(b[0]), "r"(b[1]));
}
__device__ __forceinline__ void cp_async16(uint32_t smem_dst, const void* gmem_src) {
    asm volatile("cp.async.cg.shared.global [%0], [%1], 16;"
                 :: "r"(smem_dst), "l"(gmem_src) : "memory");
}
__device__ __forceinline__ void cp_commit() {
    asm volatile("cp.async.commit_group;" ::: "memory");
}
template <int N>
__device__ __forceinline__ void cp_wait() {
    asm volatile("cp.async.wait_group %0;" :: "n"(N) : "memory");
}

// ============================= prep: split W2^T =============================
__global__ void prep_w2(const float* __restrict__ W2) {
    int idx = blockIdx.x * blockDim.x + threadIdx.x;
    if (idx < HDIM * OUTF) {
        int n = idx >> 9, k = idx & 511;
        float v = W2[(size_t)k * OUTF + n];
        __nv_bfloat16 hi = __float2bfloat16(v);
        float lo = v - __bfloat162float(hi);
        g_w2t_hi[(size_t)n * HDIM + k] = hi;
        g_w2t_lo[(size_t)n * HDIM + k] = __float2bfloat16(lo);
    }
}

// ============================= fused edge MLP =============================
__global__ __launch_bounds__(NT, 1)
void edge_mlp_tc(const float* __restrict__ src,
                 const float* __restrict__ dest,
                 const float* __restrict__ edge_attr,
                 const float* __restrict__ u,
                 const int* __restrict__ batch,
                 const float* __restrict__ W1,
                 const float* __restrict__ b1,
                 const float* __restrict__ b2,
                 float* __restrict__ out,
                 int E, int n_graphs)
{
    extern __shared__ char smc[];
    const uint32_t sb = smem_u32(smc);
    float* xs = (float*)(smc + XS_OFF);   // [64][36]
    float* ws = (float*)(smc + WS_OFF);   // [32][512]

    const int tid = threadIdx.x;
    const int lane = tid & 31;
    const int wid  = tid >> 5;
    const int e0 = blockIdx.x * BM;

    // ---------------- gather x = [src | dest | edge_attr | u[batch]] ----------------
    for (int idx = tid; idx < BM * F_IN; idx += NT) {
        int m = idx / F_IN;
        int f = idx - m * F_IN;
        int e = e0 + m;
        float v = 0.0f;
        if (e < E) {
            if (f < NODE_F)            v = src[(size_t)e * NODE_F + f];
            else if (f < 2 * NODE_F)   v = dest[(size_t)e * NODE_F + (f - NODE_F)];
            else if (f == 2 * NODE_F)  v = edge_attr[e];
            else {
                int g = batch[e];
                g = (g < 0) ? 0 : (g >= n_graphs ? n_graphs - 1 : g);
                v = u[(size_t)g * U_F + (f - 2 * NODE_F - 1)];
            }
        }
        xs[m * 36 + f] = v;
    }
    __syncthreads();

    // ---------------- GEMM1: h = relu(x @ W1 + b1) -> smem bf16 hi/lo ----------------
    {
        const int tn = tid & 31;
        const int tm = tid >> 5;
        float acc[8][16];
        #pragma unroll
        for (int g = 0; g < 4; g++) {
            float4 bb = *(const float4*)&b1[tn * 4 + g * 128];
            #pragma unroll
            for (int i = 0; i < 8; i++) {
                acc[i][g*4+0] = bb.x; acc[i][g*4+1] = bb.y;
                acc[i][g*4+2] = bb.z; acc[i][g*4+3] = bb.w;
            }
        }
        #pragma unroll
        for (int kt = 0; kt < 2; kt++) {
            const int k0 = kt * 32;
            const int nrows = (k0 + 32 <= F_IN) ? 32 : (F_IN - k0);   // 32 then 3
            for (int p = tid; p < nrows * 128; p += NT) {
                int r = p >> 7, c4 = p & 127;
                *(float4*)&ws[r * 512 + c4 * 4] =
                    *(const float4*)&W1[(size_t)(k0 + r) * 512 + c4 * 4];
            }
            __syncthreads();
            for (int k = 0; k < nrows; k++) {
                float xv[8];
                #pragma unroll
                for (int i = 0; i < 8; i++)
                    xv[i] = xs[(tm + 8*i) * 36 + k0 + k];
                #pragma unroll
                for (int g = 0; g < 4; g++) {
                    float4 w4 = *(const float4*)&ws[k * 512 + tn * 4 + g * 128];
                    #pragma unroll
                    for (int i = 0; i < 8; i++) {
                        acc[i][g*4+0] = fmaf(xv[i], w4.x, acc[i][g*4+0]);
                        acc[i][g*4+1] = fmaf(xv[i], w4.y, acc[i][g*4+1]);
                        acc[i][g*4+2] = fmaf(xv[i], w4.z, acc[i][g*4+2]);
                        acc[i][g*4+3] = fmaf(xv[i], w4.w, acc[i][g*4+3]);
                    }
                }
            }
            __syncthreads();
        }
        // relu + bf16 hi/lo split -> hs
        #pragma unroll
        for (int i = 0; i < 8; i++) {
            const int row = tm + 8*i;
            #pragma unroll
            for (int g = 0; g < 4; g++) {
                const int col = tn * 4 + g * 128;
                uint2 uh, ul;
                __nv_bfloat16* ph = (__nv_bfloat16*)&uh;
                __nv_bfloat16* pl = (__nv_bfloat16*)&ul;
                #pragma unroll
                for (int t = 0; t < 4; t++) {
                    float h = fmaxf(acc[i][g*4+t], 0.0f);
                    __nv_bfloat16 hi = __float2bfloat16(h);
                    float lo = h - __bfloat162float(hi);
                    ph[t] = hi;
                    pl[t] = __float2bfloat16(lo);
                }
                *(uint2*)(smc + HS_HI_OFF + row * HS_STRIDE_B + col * 2) = uh;
                *(uint2*)(smc + HS_LO_OFF + row * HS_STRIDE_B + col * 2) = ul;
            }
        }
        __syncthreads();   // h ready; region3 free for B tiles
    }

    // ---------------- GEMM2: out = h @ W2 + b2, mma.sync bf16x3 ----------------
    const int wm = wid >> 2;
    const int wn = wid & 3;

    const int a_row = (lane & 15);
    const int a_kof = ((lane >> 4) & 1) * 8;
    const int b_row = (lane & 7) + ((lane >> 4) & 1) * 8;
    const int b_kof = ((lane >> 3) & 1) * 8;

    #pragma unroll 1
    for (int nh = 0; nh < 2; nh++) {
        float acc2[2][8][4];
        #pragma unroll
        for (int mt = 0; mt < 2; mt++)
            #pragma unroll
            for (int nb = 0; nb < 8; nb++)
                #pragma unroll
                for (int q = 0; q < 4; q++)
                    acc2[mt][nb][q] = 0.0f;

        const int nbase = nh * 256;

        // prologue: stage k-tiles 0 and 1 (hi+lo each) via cp.async
        #pragma unroll
        for (int pk = 0; pk < 2; pk++) {
            const uint32_t buf = BBUF_OFF(pk);
            #pragma unroll
            for (int it = 0; it < 4; it++) {
                int i = tid + it * NT;            // 0..1023
                int n = i >> 2, c = i & 3;
                uint32_t d = sb + buf + n * BS_STRIDE_B + c * 16;
                size_t gofs = ((size_t)(nbase + n) * HDIM + pk * 32 + c * 8);
                cp_async16(d, g_w2t_hi + gofs);
                cp_async16(d + BTILE_BYTES, g_w2t_lo + gofs);
            }
            cp_commit();
        }

        #pragma unroll 1
        for (int kt = 0; kt < NKT; kt++) {              // 16 k-tiles (FIX: was 8)
            if (kt < NKT - 1) cp_wait<1>(); else cp_wait<0>();
            __syncthreads();

            const uint32_t bh_base = sb + BBUF_OFF(kt & 1);
            const uint32_t bl_base = bh_base + BTILE_BYTES;

            #pragma unroll
            for (int kk = 0; kk < 2; kk++) {
                const int kg = kt * 32 + kk * 16;      // global k for A
                uint32_t ah[2][4], al[2][4];
                #pragma unroll
                for (int mt = 0; mt < 2; mt++) {
                    uint32_t aoff = (uint32_t)((wm * 32 + mt * 16 + a_row) * HS_STRIDE_B
                                               + (kg + a_kof) * 2);
                    ldsm_x4(sb + HS_HI_OFF + aoff, ah[mt]);
                    ldsm_x4(sb + HS_LO_OFF + aoff, al[mt]);
                }
                #pragma unroll
                for (int nb4 = 0; nb4 < 4; nb4++) {
                    uint32_t bh[4], bl[4];
                    uint32_t boff = (uint32_t)((wn * 64 + nb4 * 16 + b_row) * BS_STRIDE_B
                                               + (kk * 16 + b_kof) * 2);
                    ldsm_x4(bh_base + boff, bh);
                    ldsm_x4(bl_base + boff, bl);
                    #pragma unroll
                    for (int mt = 0; mt < 2; mt++) {
                        #pragma unroll
                        for (int s = 0; s < 2; s++) {
                            float* d = acc2[mt][nb4 * 2 + s];
                            mma_bf16(d, ah[mt], &bh[s * 2]);   // Ah*Bh
                            mma_bf16(d, ah[mt], &bl[s * 2]);   // Ah*Bl
                            mma_bf16(d, al[mt], &bh[s * 2]);   // Al*Bh
                        }
                    }
                }
            }
            __syncthreads();

            if (kt + 2 < NKT) {                         // FIX: was kt+2 < 8
                const int pk = kt + 2;
                const uint32_t buf = BBUF_OFF(pk & 1);
                #pragma unroll
                for (int it = 0; it < 4; it++) {
                    int i = tid + it * NT;
                    int n = i >> 2, c = i & 3;
                    uint32_t d = sb + buf + n * BS_STRIDE_B + c * 16;
                    size_t gofs = ((size_t)(nbase + n) * HDIM + pk * 32 + c * 8);
                    cp_async16(d, g_w2t_hi + gofs);
                    cp_async16(d + BTILE_BYTES, g_w2t_lo + gofs);
                }
                cp_commit();
            }
        }

        // epilogue: add b2, store
        #pragma unroll
        for (int mt = 0; mt < 2; mt++) {
            const int r0 = e0 + wm * 32 + mt * 16 + (lane >> 2);
            const int r1 = r0 + 8;
            #pragma unroll
            for (int nb = 0; nb < 8; nb++) {
                const int col = nbase + wn * 64 + nb * 8 + (lane & 3) * 2;
                float2 bb = *(const float2*)&b2[col];
                if (r0 < E) {
                    float2 v0;
                    v0.x = acc2[mt][nb][0] + bb.x;
                    v0.y = acc2[mt][nb][1] + bb.y;
                    *(float2*)&out[(size_t)r0 * OUTF + col] = v0;
                }
                if (r1 < E) {
                    float2 v1;
                    v1.x = acc2[mt][nb][2] + bb.x;
                    v1.y = acc2[mt][nb][3] + bb.y;
                    *(float2*)&out[(size_t)r1 * OUTF + col] = v1;
                }
            }
        }
        __syncthreads();   // before reusing B buffers in next half
    }
}

// ============================= launch =============================
extern "C" void kernel_launch(void* const* d_in, const int* in_sizes, int n_in,
                              void* d_out, int out_size) {
    const float* src       = (const float*)d_in[0];
    const float* dest      = (const float*)d_in[1];
    const float* edge_attr = (const float*)d_in[2];
    const float* u         = (const float*)d_in[3];
    const int*   batch     = (const int*)d_in[4];     // int32 (JAX default)
    const float* W1        = (const float*)d_in[5];
    const float* b1        = (const float*)d_in[6];
    const float* W2        = (const float*)d_in[7];
    const float* b2        = (const float*)d_in[8];
    float*       out       = (float*)d_out;

    const int E        = in_sizes[0] / NODE_F;
    const int n_graphs = in_sizes[3] / U_F;

    static int configured = 0;
    if (!configured) {
        cudaFuncSetAttribute(edge_mlp_tc,
                             cudaFuncAttributeMaxDynamicSharedMemorySize, SMEM_TOTAL);
        configured = 1;
    }

    prep_w2<<<(HDIM * OUTF + 255) / 256, 256>>>(W2);

    edge_mlp_tc<<<(E + BM - 1) / BM, NT, SMEM_TOTAL>>>(
        src, dest, edge_attr, u, batch, W1, b1, b2, out, E, n_graphs);
}

// round 15
// speedup vs baseline: 3.1943x; 1.6807x over previous
#include <cuda_runtime.h>
#include <cuda_fp16.h>
#include <cstdint>

// EdgeModel: out = relu(concat(src,dest,edge_attr,u[batch]) @ W1 + b1) @ W2 + b2
// E=500000, F_IN=35, H=512, OUT=512.
// Round 14: split kernels + fp16 2-term GEMM2.
//   prep_w2:  split W2^T into fp16 hi/lo (B exact to 2^-22)
//   gemm1:    gather + GEMM1 FFMA + relu -> h fp16 scratch (2 CTAs/SM)
//   gemm2:    out = h*(Bh) + h*(Bl) + b2 via mma.sync fp16, fp32 accum,
//             CTA 128x128, KT=64, cp.async double-buffered, 2 CTAs/SM.

#define NODE_F 9
#define U_F 16
#define F_IN 35
#define HDIM 512
#define OUTF 512

// ---- gemm1 ----
#define BM1 32
#define NT1 256
#define G1_SMEM ((BM1 * 36 + F_IN * 512) * 4)   // 76288 B

// ---- gemm2 ----
#define TM2 128
#define TN2 128
#define KT2 64
#define NKT2 (HDIM / KT2)        // 8
#define NT2 256
#define AS_B 144                 // row stride bytes: 64 fp16 = 128 B + 16 pad
#define TILE_B (128 * AS_B)      // 18432 B
#define A_OFF(b)  ((b) * TILE_B)
#define BH_OFF(b) (2 * TILE_B + (b) * 2 * TILE_B)
#define G2_SMEM (6 * TILE_B)     // 110592 B -> 2 CTAs/SM

#define EMAX 500096              // 3907 * 128

// ---------------- static scratch ----------------
__device__ __align__(16) __half g_h[(size_t)EMAX * HDIM];      // 512 MB
__device__ __align__(16) __half g_w2t_hi[HDIM * OUTF];         // [n][k]
__device__ __align__(16) __half g_w2t_lo[HDIM * OUTF];

// ---------------- PTX helpers (baseline sm_80+) ----------------
__device__ __forceinline__ uint32_t smem_u32(const void* p) {
    uint32_t a;
    asm("{ .reg .u64 t; cvta.to.shared.u64 t, %1; cvt.u32.u64 %0, t; }" : "=r"(a) : "l"(p));
    return a;
}
__device__ __forceinline__ void ldsm_x4(uint32_t addr, uint32_t* r) {
    asm volatile("ldmatrix.sync.aligned.m8n8.x4.shared.b16 {%0,%1,%2,%3}, [%4];"
                 : "=r"(r[0]), "=r"(r[1]), "=r"(r[2]), "=r"(r[3]) : "r"(addr));
}
__device__ __forceinline__ void mma_f16(float* d, const uint32_t* a, const uint32_t* b) {
    asm volatile(
        "mma.sync.aligned.m16n8k16.row.col.f32.f16.f16.f32 "
        "{%0,%1,%2,%3}, {%4,%5,%6,%7}, {%8,%9}, {%0,%1,%2,%3};"
        : "+f"(d[0]), "+f"(d[1]), "+f"(d[2]), "+f"(d[3])
        : "r"(a[0]), "r"(a[1]), "r"(a[2]), "r"(a[3]), "r"(b[0]), "r"(b[1]));
}
__device__ __forceinline__ void cp_async16(uint32_t smem_dst, const void* gmem_src) {
    asm volatile("cp.async.cg.shared.global [%0], [%1], 16;"
                 :: "r"(smem_dst), "l"(gmem_src) : "memory");
}
__device__ __forceinline__ void cp_commit() {
    asm volatile("cp.async.commit_group;" ::: "memory");
}
template <int N>
__device__ __forceinline__ void cp_wait() {
    asm volatile("cp.async.wait_group %0;" :: "n"(N) : "memory");
}

// ============================= prep: split W2^T (fp16 hi/lo) =============================
__global__ void prep_w2(const float* __restrict__ W2) {
    int idx = blockIdx.x * blockDim.x + threadIdx.x;
    if (idx < HDIM * OUTF) {
        int n = idx >> 9, k = idx & 511;
        float v = W2[(size_t)k * OUTF + n];
        __half hi = __float2half_rn(v);
        float lo = v - __half2float(hi);
        g_w2t_hi[(size_t)n * HDIM + k] = hi;
        g_w2t_lo[(size_t)n * HDIM + k] = __float2half_rn(lo);
    }
}

// ============================= GEMM1: h = relu(x @ W1 + b1) -> fp16 =============================
__global__ __launch_bounds__(NT1, 2)
void gemm1_ffma(const float* __restrict__ src,
                const float* __restrict__ dest,
                const float* __restrict__ edge_attr,
                const float* __restrict__ u,
                const int* __restrict__ batch,
                const float* __restrict__ W1,
                const float* __restrict__ b1,
                int E, int n_graphs)
{
    extern __shared__ float sm1[];
    float* xs = sm1;                 // [32][36]
    float* ws = sm1 + BM1 * 36;      // [35][512]

    const int tid = threadIdx.x;
    const int tn  = tid & 31;        // 32 col-groups: cols tn*4 + g*128, g<4
    const int tm  = tid >> 5;        // 8 row-groups: rows tm + 8*i, i<4
    const int e0  = blockIdx.x * BM1;

    // gather x
    for (int idx = tid; idx < BM1 * F_IN; idx += NT1) {
        int m = idx / F_IN;
        int f = idx - m * F_IN;
        int e = e0 + m;
        float v = 0.0f;
        if (e < E) {
            if (f < NODE_F)            v = src[(size_t)e * NODE_F + f];
            else if (f < 2 * NODE_F)   v = dest[(size_t)e * NODE_F + (f - NODE_F)];
            else if (f == 2 * NODE_F)  v = edge_attr[e];
            else {
                int g = batch[e];
                g = (g < 0) ? 0 : (g >= n_graphs ? n_graphs - 1 : g);
                v = u[(size_t)g * U_F + (f - 2 * NODE_F - 1)];
            }
        }
        xs[m * 36 + f] = v;
    }
    // stage full W1 [35][512]
    for (int p = tid; p < F_IN * 128; p += NT1) {
        int r = p >> 7, c4 = p & 127;
        *(float4*)&ws[r * 512 + c4 * 4] = *(const float4*)&W1[(size_t)r * 512 + c4 * 4];
    }
    __syncthreads();

    float acc[4][16];
    #pragma unroll
    for (int g = 0; g < 4; g++) {
        float4 bb = *(const float4*)&b1[tn * 4 + g * 128];
        #pragma unroll
        for (int i = 0; i < 4; i++) {
            acc[i][g*4+0] = bb.x; acc[i][g*4+1] = bb.y;
            acc[i][g*4+2] = bb.z; acc[i][g*4+3] = bb.w;
        }
    }

    #pragma unroll 1
    for (int k = 0; k < F_IN; k++) {
        float xv[4];
        #pragma unroll
        for (int i = 0; i < 4; i++)
            xv[i] = xs[(tm + 8*i) * 36 + k];
        #pragma unroll
        for (int g = 0; g < 4; g++) {
            float4 w4 = *(const float4*)&ws[k * 512 + tn * 4 + g * 128];
            #pragma unroll
            for (int i = 0; i < 4; i++) {
                acc[i][g*4+0] = fmaf(xv[i], w4.x, acc[i][g*4+0]);
                acc[i][g*4+1] = fmaf(xv[i], w4.y, acc[i][g*4+1]);
                acc[i][g*4+2] = fmaf(xv[i], w4.z, acc[i][g*4+2]);
                acc[i][g*4+3] = fmaf(xv[i], w4.w, acc[i][g*4+3]);
            }
        }
    }

    // relu -> fp16 -> g_h
    #pragma unroll
    for (int i = 0; i < 4; i++) {
        const int e = e0 + tm + 8*i;
        if (e < E) {
            #pragma unroll
            for (int g = 0; g < 4; g++) {
                const int col = tn * 4 + g * 128;
                __half2 p0 = __floats2half2_rn(fmaxf(acc[i][g*4+0], 0.0f),
                                               fmaxf(acc[i][g*4+1], 0.0f));
                __half2 p1 = __floats2half2_rn(fmaxf(acc[i][g*4+2], 0.0f),
                                               fmaxf(acc[i][g*4+3], 0.0f));
                uint2 uv;
                uv.x = *reinterpret_cast<uint32_t*>(&p0);
                uv.y = *reinterpret_cast<uint32_t*>(&p1);
                *(uint2*)&g_h[(size_t)e * HDIM + col] = uv;
            }
        }
    }
}

// ============================= GEMM2: out = h @ W2 + b2 =============================
__device__ __forceinline__ void stage_tiles(uint32_t sb, int buf, int kt,
                                            int e0, int nbase, int tid) {
    const int k0 = kt * KT2;
    const uint32_t a_dst  = sb + A_OFF(buf);
    const uint32_t bh_dst = sb + BH_OFF(buf);
    const uint32_t bl_dst = bh_dst + TILE_B;
    #pragma unroll
    for (int it = 0; it < 4; it++) {
        int i = tid + it * NT2;          // 0..1023
        int r = i >> 3, c = i & 7;
        uint32_t soff = (uint32_t)(r * AS_B + c * 16);
        size_t ga = (size_t)(e0 + r) * HDIM + k0 + c * 8;
        size_t gb = (size_t)(nbase + r) * HDIM + k0 + c * 8;
        cp_async16(a_dst + soff,  g_h + ga);
        cp_async16(bh_dst + soff, g_w2t_hi + gb);
        cp_async16(bl_dst + soff, g_w2t_lo + gb);
    }
    cp_commit();
}

__global__ __launch_bounds__(NT2, 2)
void gemm2_tc(const float* __restrict__ b2, float* __restrict__ out, int E)
{
    extern __shared__ char smc[];
    const uint32_t sb = smem_u32(smc);
    const int tid  = threadIdx.x;
    const int lane = tid & 31;
    const int wid  = tid >> 5;
    const int wm   = wid >> 1;       // 4 m-blocks of 32
    const int wn   = wid & 1;        // 2 n-blocks of 64
    const int e0    = blockIdx.y * TM2;    // M tile (3907)
    const int nbase = blockIdx.x * TN2;    // N tile (4); x-major -> A tile L2 reuse

    const int a_row = (lane & 15);
    const int a_kof = ((lane >> 4) & 1) * 8;
    const int b_row = (lane & 7) + ((lane >> 4) & 1) * 8;
    const int b_kof = ((lane >> 3) & 1) * 8;

    float acc2[2][8][4];
    #pragma unroll
    for (int mt = 0; mt < 2; mt++)
        #pragma unroll
        for (int nb = 0; nb < 8; nb++)
            #pragma unroll
            for (int q = 0; q < 4; q++)
                acc2[mt][nb][q] = 0.0f;

    // prologue
    stage_tiles(sb, 0, 0, e0, nbase, tid);
    stage_tiles(sb, 1, 1, e0, nbase, tid);

    #pragma unroll 1
    for (int kt = 0; kt < NKT2; kt++) {
        if (kt < NKT2 - 1) cp_wait<1>(); else cp_wait<0>();
        __syncthreads();

        const uint32_t abuf = sb + A_OFF(kt & 1);
        const uint32_t bhb  = sb + BH_OFF(kt & 1);
        const uint32_t blb  = bhb + TILE_B;

        #pragma unroll
        for (int kk = 0; kk < 4; kk++) {
            uint32_t ah[2][4];
            #pragma unroll
            for (int mt = 0; mt < 2; mt++) {
                uint32_t aoff = (uint32_t)((wm * 32 + mt * 16 + a_row) * AS_B
                                           + (kk * 16 + a_kof) * 2);
                ldsm_x4(abuf + aoff, ah[mt]);
            }
            #pragma unroll
            for (int nb4 = 0; nb4 < 4; nb4++) {
                uint32_t bh[4], bl[4];
                uint32_t boff = (uint32_t)((wn * 64 + nb4 * 16 + b_row) * AS_B
                                           + (kk * 16 + b_kof) * 2);
                ldsm_x4(bhb + boff, bh);
                ldsm_x4(blb + boff, bl);
                #pragma unroll
                for (int mt = 0; mt < 2; mt++) {
                    #pragma unroll
                    for (int s = 0; s < 2; s++) {
                        float* d = acc2[mt][nb4 * 2 + s];
                        mma_f16(d, ah[mt], &bh[s * 2]);   // A * Bh
                        mma_f16(d, ah[mt], &bl[s * 2]);   // A * Bl
                    }
                }
            }
        }
        __syncthreads();

        if (kt + 2 < NKT2)
            stage_tiles(sb, kt & 1, kt + 2, e0, nbase, tid);
    }

    // epilogue: add b2, store
    #pragma unroll
    for (int mt = 0; mt < 2; mt++) {
        const int r0 = e0 + wm * 32 + mt * 16 + (lane >> 2);
        const int r1 = r0 + 8;
        #pragma unroll
        for (int nb = 0; nb < 8; nb++) {
            const int col = nbase + wn * 64 + nb * 8 + (lane & 3) * 2;
            float2 bb = *(const float2*)&b2[col];
            if (r0 < E) {
                float2 v0;
                v0.x = acc2[mt][nb][0] + bb.x;
                v0.y = acc2[mt][nb][1] + bb.y;
                *(float2*)&out[(size_t)r0 * OUTF + col] = v0;
            }
            if (r1 < E) {
                float2 v1;
                v1.x = acc2[mt][nb][2] + bb.x;
                v1.y = acc2[mt][nb][3] + bb.y;
                *(float2*)&out[(size_t)r1 * OUTF + col] = v1;
            }
        }
    }
}

// ============================= launch =============================
extern "C" void kernel_launch(void* const* d_in, const int* in_sizes, int n_in,
                              void* d_out, int out_size) {
    const float* src       = (const float*)d_in[0];
    const float* dest      = (const float*)d_in[1];
    const float* edge_attr = (const float*)d_in[2];
    const float* u         = (const float*)d_in[3];
    const int*   batch     = (const int*)d_in[4];     // int32 (JAX default)
    const float* W1        = (const float*)d_in[5];
    const float* b1        = (const float*)d_in[6];
    const float* W2        = (const float*)d_in[7];
    const float* b2        = (const float*)d_in[8];
    float*       out       = (float*)d_out;

    const int E        = in_sizes[0] / NODE_F;
    const int n_graphs = in_sizes[3] / U_F;

    static int configured = 0;
    if (!configured) {
        cudaFuncSetAttribute(gemm1_ffma,
                             cudaFuncAttributeMaxDynamicSharedMemorySize, G1_SMEM);
        cudaFuncSetAttribute(gemm2_tc,
                             cudaFuncAttributeMaxDynamicSharedMemorySize, G2_SMEM);
        configured = 1;
    }

    prep_w2<<<(HDIM * OUTF + 255) / 256, 256>>>(W2);

    gemm1_ffma<<<(E + BM1 - 1) / BM1, NT1, G1_SMEM>>>(
        src, dest, edge_attr, u, batch, W1, b1, E, n_graphs);

    dim3 g2(4, (E + TM2 - 1) / TM2);
    gemm2_tc<<<g2, NT2, G2_SMEM>>>(b2, out, E);
}

// round 16
// speedup vs baseline: 4.2242x; 1.3224x over previous
#include <cuda_runtime.h>
#include <cuda_fp16.h>
#include <cstdint>

// EdgeModel: out = relu(concat(src,dest,edge_attr,u[batch]) @ W1 + b1) @ W2 + b2
// E=500000, F_IN=35, H=512, OUT=512.
// Round 16: single-term fp16 GEMM2 (measured 2-term rel_err 2.06e-4 = A-side
// rounding only; dropping A*Bl adds an independent equal term -> ~2.9e-4,
// 3.4x under threshold) + 3-stage cp.async pipeline.
//   prep_w2:  W2^T -> fp16
//   gemm1:    gather + GEMM1 FFMA + relu -> h fp16 scratch (2 CTAs/SM)
//   gemm2:    out = h @ W2 + b2 via mma.sync fp16, fp32 accum,
//             CTA 128x128, KT=64, 3-stage cp.async, 2 CTAs/SM.

#define NODE_F 9
#define U_F 16
#define F_IN 35
#define HDIM 512
#define OUTF 512

// ---- gemm1 ----
#define BM1 32
#define NT1 256
#define G1_SMEM ((BM1 * 36 + F_IN * 512) * 4)   // 76288 B

// ---- gemm2 ----
#define TM2 128
#define TN2 128
#define KT2 64
#define NKT2 (HDIM / KT2)        // 8
#define NT2 256
#define NSTAGE 3
#define AS_B 144                 // row stride bytes: 64 fp16 = 128 B + 16 pad
#define TILE_B (128 * AS_B)      // 18432 B
#define STG_OFF(s) ((s) * 2 * TILE_B)           // [A | B] per stage
#define G2_SMEM (NSTAGE * 2 * TILE_B)           // 110592 B -> 2 CTAs/SM

#define EMAX 500096              // 3907 * 128

// ---------------- static scratch ----------------
__device__ __align__(16) __half g_h[(size_t)EMAX * HDIM];      // 512 MB
__device__ __align__(16) __half g_w2t[HDIM * OUTF];            // [n][k] fp16

// ---------------- PTX helpers (baseline sm_80+) ----------------
__device__ __forceinline__ uint32_t smem_u32(const void* p) {
    uint32_t a;
    asm("{ .reg .u64 t; cvta.to.shared.u64 t, %1; cvt.u32.u64 %0, t; }" : "=r"(a) : "l"(p));
    return a;
}
__device__ __forceinline__ void ldsm_x4(uint32_t addr, uint32_t* r) {
    asm volatile("ldmatrix.sync.aligned.m8n8.x4.shared.b16 {%0,%1,%2,%3}, [%4];"
                 : "=r"(r[0]), "=r"(r[1]), "=r"(r[2]), "=r"(r[3]) : "r"(addr));
}
__device__ __forceinline__ void mma_f16(float* d, const uint32_t* a, const uint32_t* b) {
    asm volatile(
        "mma.sync.aligned.m16n8k16.row.col.f32.f16.f16.f32 "
        "{%0,%1,%2,%3}, {%4,%5,%6,%7}, {%8,%9}, {%0,%1,%2,%3};"
        : "+f"(d[0]), "+f"(d[1]), "+f"(d[2]), "+f"(d[3])
        : "r"(a[0]), "r"(a[1]), "r"(a[2]), "r"(a[3]), "r"(b[0]), "r"(b[1]));
}
__device__ __forceinline__ void cp_async16(uint32_t smem_dst, const void* gmem_src) {
    asm volatile("cp.async.cg.shared.global [%0], [%1], 16;"
                 :: "r"(smem_dst), "l"(gmem_src) : "memory");
}
__device__ __forceinline__ void cp_commit() {
    asm volatile("cp.async.commit_group;" ::: "memory");
}
template <int N>
__device__ __forceinline__ void cp_wait() {
    asm volatile("cp.async.wait_group %0;" :: "n"(N) : "memory");
}

// ============================= prep: W2^T -> fp16 =============================
__global__ void prep_w2(const float* __restrict__ W2) {
    int idx = blockIdx.x * blockDim.x + threadIdx.x;
    if (idx < HDIM * OUTF) {
        int n = idx >> 9, k = idx & 511;
        g_w2t[(size_t)n * HDIM + k] = __float2half_rn(W2[(size_t)k * OUTF + n]);
    }
}

// ============================= GEMM1: h = relu(x @ W1 + b1) -> fp16 =============================
__global__ __launch_bounds__(NT1, 2)
void gemm1_ffma(const float* __restrict__ src,
                const float* __restrict__ dest,
                const float* __restrict__ edge_attr,
                const float* __restrict__ u,
                const int* __restrict__ batch,
                const float* __restrict__ W1,
                const float* __restrict__ b1,
                int E, int n_graphs)
{
    extern __shared__ float sm1[];
    float* xs = sm1;                 // [32][36]
    float* ws = sm1 + BM1 * 36;      // [35][512]

    const int tid = threadIdx.x;
    const int tn  = tid & 31;
    const int tm  = tid >> 5;
    const int e0  = blockIdx.x * BM1;

    // gather x
    for (int idx = tid; idx < BM1 * F_IN; idx += NT1) {
        int m = idx / F_IN;
        int f = idx - m * F_IN;
        int e = e0 + m;
        float v = 0.0f;
        if (e < E) {
            if (f < NODE_F)            v = src[(size_t)e * NODE_F + f];
            else if (f < 2 * NODE_F)   v = dest[(size_t)e * NODE_F + (f - NODE_F)];
            else if (f == 2 * NODE_F)  v = edge_attr[e];
            else {
                int g = batch[e];
                g = (g < 0) ? 0 : (g >= n_graphs ? n_graphs - 1 : g);
                v = u[(size_t)g * U_F + (f - 2 * NODE_F - 1)];
            }
        }
        xs[m * 36 + f] = v;
    }
    // stage full W1 [35][512]
    for (int p = tid; p < F_IN * 128; p += NT1) {
        int r = p >> 7, c4 = p & 127;
        *(float4*)&ws[r * 512 + c4 * 4] = *(const float4*)&W1[(size_t)r * 512 + c4 * 4];
    }
    __syncthreads();

    float acc[4][16];
    #pragma unroll
    for (int g = 0; g < 4; g++) {
        float4 bb = *(const float4*)&b1[tn * 4 + g * 128];
        #pragma unroll
        for (int i = 0; i < 4; i++) {
            acc[i][g*4+0] = bb.x; acc[i][g*4+1] = bb.y;
            acc[i][g*4+2] = bb.z; acc[i][g*4+3] = bb.w;
        }
    }

    #pragma unroll 1
    for (int k = 0; k < F_IN; k++) {
        float xv[4];
        #pragma unroll
        for (int i = 0; i < 4; i++)
            xv[i] = xs[(tm + 8*i) * 36 + k];
        #pragma unroll
        for (int g = 0; g < 4; g++) {
            float4 w4 = *(const float4*)&ws[k * 512 + tn * 4 + g * 128];
            #pragma unroll
            for (int i = 0; i < 4; i++) {
                acc[i][g*4+0] = fmaf(xv[i], w4.x, acc[i][g*4+0]);
                acc[i][g*4+1] = fmaf(xv[i], w4.y, acc[i][g*4+1]);
                acc[i][g*4+2] = fmaf(xv[i], w4.z, acc[i][g*4+2]);
                acc[i][g*4+3] = fmaf(xv[i], w4.w, acc[i][g*4+3]);
            }
        }
    }

    // relu -> fp16 -> g_h
    #pragma unroll
    for (int i = 0; i < 4; i++) {
        const int e = e0 + tm + 8*i;
        if (e < E) {
            #pragma unroll
            for (int g = 0; g < 4; g++) {
                const int col = tn * 4 + g * 128;
                __half2 p0 = __floats2half2_rn(fmaxf(acc[i][g*4+0], 0.0f),
                                               fmaxf(acc[i][g*4+1], 0.0f));
                __half2 p1 = __floats2half2_rn(fmaxf(acc[i][g*4+2], 0.0f),
                                               fmaxf(acc[i][g*4+3], 0.0f));
                uint2 uv;
                uv.x = *reinterpret_cast<uint32_t*>(&p0);
                uv.y = *reinterpret_cast<uint32_t*>(&p1);
                *(uint2*)&g_h[(size_t)e * HDIM + col] = uv;
            }
        }
    }
}

// ============================= GEMM2: out = h @ W2 + b2 =============================
__device__ __forceinline__ void stage_tiles(uint32_t sb, int buf, int kt,
                                            int e0, int nbase, int tid) {
    const int k0 = kt * KT2;
    const uint32_t a_dst = sb + STG_OFF(buf);
    const uint32_t b_dst = a_dst + TILE_B;
    #pragma unroll
    for (int it = 0; it < 4; it++) {
        int i = tid + it * NT2;          // 0..1023
        int r = i >> 3, c = i & 7;
        uint32_t soff = (uint32_t)(r * AS_B + c * 16);
        size_t ga = (size_t)(e0 + r) * HDIM + k0 + c * 8;
        size_t gb = (size_t)(nbase + r) * HDIM + k0 + c * 8;
        cp_async16(a_dst + soff, g_h + ga);
        cp_async16(b_dst + soff, g_w2t + gb);
    }
    cp_commit();
}

__global__ __launch_bounds__(NT2, 2)
void gemm2_tc(const float* __restrict__ b2, float* __restrict__ out, int E)
{
    extern __shared__ char smc[];
    const uint32_t sb = smem_u32(smc);
    const int tid  = threadIdx.x;
    const int lane = tid & 31;
    const int wid  = tid >> 5;
    const int wm   = wid >> 1;       // 4 m-blocks of 32
    const int wn   = wid & 1;        // 2 n-blocks of 64
    const int e0    = blockIdx.y * TM2;    // M tile (3907)
    const int nbase = blockIdx.x * TN2;    // N tile (4); x-major -> A tile L2 reuse

    const int a_row = (lane & 15);
    const int a_kof = ((lane >> 4) & 1) * 8;
    const int b_row = (lane & 7) + ((lane >> 4) & 1) * 8;
    const int b_kof = ((lane >> 3) & 1) * 8;

    float acc2[2][8][4];
    #pragma unroll
    for (int mt = 0; mt < 2; mt++)
        #pragma unroll
        for (int nb = 0; nb < 8; nb++)
            #pragma unroll
            for (int q = 0; q < 4; q++)
                acc2[mt][nb][q] = 0.0f;

    // prologue: stage 3 k-tiles
    stage_tiles(sb, 0, 0, e0, nbase, tid);
    stage_tiles(sb, 1, 1, e0, nbase, tid);
    stage_tiles(sb, 2, 2, e0, nbase, tid);

    int buf = 0;
    #pragma unroll 1
    for (int kt = 0; kt < NKT2; kt++) {
        const int rem = NKT2 - 1 - kt;     // stages still in flight after this one
        if (rem >= 2)      cp_wait<2>();
        else if (rem == 1) cp_wait<1>();
        else               cp_wait<0>();
        __syncthreads();

        const uint32_t abuf = sb + STG_OFF(buf);
        const uint32_t bbuf = abuf + TILE_B;

        #pragma unroll
        for (int kk = 0; kk < 4; kk++) {
            uint32_t ah[2][4];
            #pragma unroll
            for (int mt = 0; mt < 2; mt++) {
                uint32_t aoff = (uint32_t)((wm * 32 + mt * 16 + a_row) * AS_B
                                           + (kk * 16 + a_kof) * 2);
                ldsm_x4(abuf + aoff, ah[mt]);
            }
            #pragma unroll
            for (int nb4 = 0; nb4 < 4; nb4++) {
                uint32_t bh[4];
                uint32_t boff = (uint32_t)((wn * 64 + nb4 * 16 + b_row) * AS_B
                                           + (kk * 16 + b_kof) * 2);
                ldsm_x4(bbuf + boff, bh);
                #pragma unroll
                for (int mt = 0; mt < 2; mt++) {
                    #pragma unroll
                    for (int s = 0; s < 2; s++) {
                        mma_f16(acc2[mt][nb4 * 2 + s], ah[mt], &bh[s * 2]);
                    }
                }
            }
        }
        __syncthreads();

        if (kt + NSTAGE < NKT2)
            stage_tiles(sb, buf, kt + NSTAGE, e0, nbase, tid);

        buf = (buf == NSTAGE - 1) ? 0 : buf + 1;
    }

    // epilogue: add b2, store
    #pragma unroll
    for (int mt = 0; mt < 2; mt++) {
        const int r0 = e0 + wm * 32 + mt * 16 + (lane >> 2);
        const int r1 = r0 + 8;
        #pragma unroll
        for (int nb = 0; nb < 8; nb++) {
            const int col = nbase + wn * 64 + nb * 8 + (lane & 3) * 2;
            float2 bb = *(const float2*)&b2[col];
            if (r0 < E) {
                float2 v0;
                v0.x = acc2[mt][nb][0] + bb.x;
                v0.y = acc2[mt][nb][1] + bb.y;
                *(float2*)&out[(size_t)r0 * OUTF + col] = v0;
            }
            if (r1 < E) {
                float2 v1;
                v1.x = acc2[mt][nb][2] + bb.x;
                v1.y = acc2[mt][nb][3] + bb.y;
                *(float2*)&out[(size_t)r1 * OUTF + col] = v1;
            }
        }
    }
}

// ============================= launch =============================
extern "C" void kernel_launch(void* const* d_in, const int* in_sizes, int n_in,
                              void* d_out, int out_size) {
    const float* src       = (const float*)d_in[0];
    const float* dest      = (const float*)d_in[1];
    const float* edge_attr = (const float*)d_in[2];
    const float* u         = (const float*)d_in[3];
    const int*   batch     = (const int*)d_in[4];     // int32 (JAX default)
    const float* W1        = (const float*)d_in[5];
    const float* b1        = (const float*)d_in[6];
    const float* W2        = (const float*)d_in[7];
    const float* b2        = (const float*)d_in[8];
    float*       out       = (float*)d_out;

    const int E        = in_sizes[0] / NODE_F;
    const int n_graphs = in_sizes[3] / U_F;

    static int configured = 0;
    if (!configured) {
        cudaFuncSetAttribute(gemm1_ffma,
                             cudaFuncAttributeMaxDynamicSharedMemorySize, G1_SMEM);
        cudaFuncSetAttribute(gemm2_tc,
                             cudaFuncAttributeMaxDynamicSharedMemorySize, G2_SMEM);
        configured = 1;
    }

    prep_w2<<<(HDIM * OUTF + 255) / 256, 256>>>(W2);

    gemm1_ffma<<<(E + BM1 - 1) / BM1, NT1, G1_SMEM>>>(
        src, dest, edge_attr, u, batch, W1, b1, E, n_graphs);

    dim3 g2(4, (E + TM2 - 1) / TM2);
    gemm2_tc<<<g2, NT2, G2_SMEM>>>(b2, out, E);
}

// round 17
// speedup vs baseline: 4.4371x; 1.0504x over previous
#include <cuda_runtime.h>
#include <cuda_fp16.h>
#include <cstdint>

// EdgeModel: out = relu(concat(src,dest,edge_attr,u[batch]) @ W1 + b1) @ W2 + b2
// E=500000, F_IN=35, H=512, OUT=512.
// Round 17: FULLY FUSED single kernel, 128 edges/CTA, 512 threads (16 warps):
//   gather -> GEMM1 FFMA fp32 -> h fp16 in SMEM (no DRAM round-trip)
//   -> GEMM2 mma.sync fp16 (A ldmatrix direct from h smem, B cp.async 2-stage),
//   N streamed in 2 halves of 256. prep_w2 makes fp16 W2^T once.

#define NODE_F 9
#define U_F 16
#define F_IN 35
#define HDIM 512
#define OUTF 512
#define BM 128
#define NT 512

// ---------------- smem byte layout ----------------
// hs   : [128][520 fp16]  = 133120 B   (h, GEMM2 A operand; 520 = 512+8 pad)
// R2   : union {
//          GEMM1: xs fp32 [128][36] (18432) | ws fp32 [35][512] (71680)  = 90112
//          GEMM2: B stages 2 x [256][72 fp16] (2 x 36864 = 73728)
//        }
#define HS_B    1040
#define HS_OFF  0
#define R2_OFF  133120
#define XS_OFF  R2_OFF
#define WS_OFF  (R2_OFF + 18432)
#define BSTG_B  144
#define BTILE   (256 * BSTG_B)            // 36864
#define BSTG_OFF(s) (R2_OFF + (s) * BTILE)
#define SMEM_TOTAL (R2_OFF + 90112)       // 223232 B

#define KT2   64
#define NKT2  (HDIM / KT2)                // 8

// ---------------- static scratch ----------------
__device__ __align__(16) __half g_w2t[HDIM * OUTF];   // [n][k] = W2[k][n], fp16

// ---------------- PTX helpers (baseline sm_80+) ----------------
__device__ __forceinline__ uint32_t smem_u32(const void* p) {
    uint32_t a;
    asm("{ .reg .u64 t; cvta.to.shared.u64 t, %1; cvt.u32.u64 %0, t; }" : "=r"(a) : "l"(p));
    return a;
}
__device__ __forceinline__ void ldsm_x4(uint32_t addr, uint32_t* r) {
    asm volatile("ldmatrix.sync.aligned.m8n8.x4.shared.b16 {%0,%1,%2,%3}, [%4];"
                 : "=r"(r[0]), "=r"(r[1]), "=r"(r[2]), "=r"(r[3]) : "r"(addr));
}
__device__ __forceinline__ void mma_f16(float* d, const uint32_t* a, const uint32_t* b) {
    asm volatile(
        "mma.sync.aligned.m16n8k16.row.col.f32.f16.f16.f32 "
        "{%0,%1,%2,%3}, {%4,%5,%6,%7}, {%8,%9}, {%0,%1,%2,%3};"
        : "+f"(d[0]), "+f"(d[1]), "+f"(d[2]), "+f"(d[3])
        : "r"(a[0]), "r"(a[1]), "r"(a[2]), "r"(a[3]), "r"(b[0]), "r"(b[1]));
}
__device__ __forceinline__ void cp_async16(uint32_t smem_dst, const void* gmem_src) {
    asm volatile("cp.async.cg.shared.global [%0], [%1], 16;"
                 :: "r"(smem_dst), "l"(gmem_src) : "memory");
}
__device__ __forceinline__ void cp_commit() {
    asm volatile("cp.async.commit_group;" ::: "memory");
}
template <int N>
__device__ __forceinline__ void cp_wait() {
    asm volatile("cp.async.wait_group %0;" :: "n"(N) : "memory");
}

// ============================= prep: W2^T -> fp16 =============================
__global__ void prep_w2(const float* __restrict__ W2) {
    int idx = blockIdx.x * blockDim.x + threadIdx.x;
    if (idx < HDIM * OUTF) {
        int n = idx >> 9, k = idx & 511;
        g_w2t[(size_t)n * HDIM + k] = __float2half_rn(W2[(size_t)k * OUTF + n]);
    }
}

// ============================= fused edge MLP =============================
__device__ __forceinline__ void stage_b(uint32_t sb, int buf, int kt, int nbase, int tid) {
    const int k0 = kt * KT2;
    const uint32_t b_dst = sb + BSTG_OFF(buf);
    #pragma unroll
    for (int it = 0; it < 4; it++) {
        int i = tid + it * NT;           // 0..2047 ; 256 rows x 8 chunks
        int r = i >> 3, c = i & 7;
        cp_async16(b_dst + (uint32_t)(r * BSTG_B + c * 16),
                   g_w2t + (size_t)(nbase + r) * HDIM + k0 + c * 8);
    }
    cp_commit();
}

__global__ __launch_bounds__(NT, 1)
void edge_mlp_fused(const float* __restrict__ src,
                    const float* __restrict__ dest,
                    const float* __restrict__ edge_attr,
                    const float* __restrict__ u,
                    const int* __restrict__ batch,
                    const float* __restrict__ W1,
                    const float* __restrict__ b1,
                    const float* __restrict__ b2,
                    float* __restrict__ out,
                    int E, int n_graphs)
{
    extern __shared__ char smc[];
    const uint32_t sb = smem_u32(smc);
    float* xs = (float*)(smc + XS_OFF);   // [128][36]
    float* ws = (float*)(smc + WS_OFF);   // [35][512]

    const int tid  = threadIdx.x;
    const int lane = tid & 31;
    const int wid  = tid >> 5;
    const int e0   = blockIdx.x * BM;

    // ---------------- gather x ----------------
    for (int idx = tid; idx < BM * F_IN; idx += NT) {
        int m = idx / F_IN;
        int f = idx - m * F_IN;
        int e = e0 + m;
        float v = 0.0f;
        if (e < E) {
            if (f < NODE_F)            v = src[(size_t)e * NODE_F + f];
            else if (f < 2 * NODE_F)   v = dest[(size_t)e * NODE_F + (f - NODE_F)];
            else if (f == 2 * NODE_F)  v = edge_attr[e];
            else {
                int g = batch[e];
                g = (g < 0) ? 0 : (g >= n_graphs ? n_graphs - 1 : g);
                v = u[(size_t)g * U_F + (f - 2 * NODE_F - 1)];
            }
        }
        xs[m * 36 + f] = v;
    }
    // stage full W1 [35][512] fp32
    for (int p = tid; p < F_IN * 128; p += NT) {
        int r = p >> 7, c4 = p & 127;
        *(float4*)&ws[r * 512 + c4 * 4] = *(const float4*)&W1[(size_t)r * 512 + c4 * 4];
    }
    __syncthreads();

    // ---------------- GEMM1: h = relu(x @ W1 + b1) -> hs fp16, 2 N-halves ----------------
    {
        const int tn = tid & 63;          // 64 col-groups of 4 (covers 256 per half)
        const int tm = tid >> 6;          // 8 row-groups; rows tm + 8*i, i<16
        #pragma unroll 1
        for (int nh = 0; nh < 2; nh++) {
            const int c0 = nh * 256 + tn * 4;
            float4 bb = *(const float4*)&b1[c0];
            float acc[16][4];
            #pragma unroll
            for (int i = 0; i < 16; i++) {
                acc[i][0] = bb.x; acc[i][1] = bb.y; acc[i][2] = bb.z; acc[i][3] = bb.w;
            }
            #pragma unroll 1
            for (int k = 0; k < F_IN; k++) {
                float4 w4 = *(const float4*)&ws[k * 512 + c0];
                #pragma unroll
                for (int i = 0; i < 16; i++) {
                    float xv = xs[(tm + 8*i) * 36 + k];
                    acc[i][0] = fmaf(xv, w4.x, acc[i][0]);
                    acc[i][1] = fmaf(xv, w4.y, acc[i][1]);
                    acc[i][2] = fmaf(xv, w4.z, acc[i][2]);
                    acc[i][3] = fmaf(xv, w4.w, acc[i][3]);
                }
            }
            #pragma unroll
            for (int i = 0; i < 16; i++) {
                const int row = tm + 8*i;
                __half2 p0 = __floats2half2_rn(fmaxf(acc[i][0], 0.0f), fmaxf(acc[i][1], 0.0f));
                __half2 p1 = __floats2half2_rn(fmaxf(acc[i][2], 0.0f), fmaxf(acc[i][3], 0.0f));
                uint2 uv;
                uv.x = *reinterpret_cast<uint32_t*>(&p0);
                uv.y = *reinterpret_cast<uint32_t*>(&p1);
                *(uint2*)(smc + HS_OFF + row * HS_B + c0 * 2) = uv;
            }
        }
        __syncthreads();   // hs complete; R2 region free for B stages
    }

    // ---------------- GEMM2: out = h @ W2 + b2 ----------------
    const int wm = wid >> 2;     // 4 m-blocks of 32
    const int wn = wid & 3;      // 4 n-blocks of 64 (per 256-half)

    const int a_row = (lane & 15);
    const int a_kof = ((lane >> 4) & 1) * 8;
    const int b_row = (lane & 7) + ((lane >> 4) & 1) * 8;
    const int b_kof = ((lane >> 3) & 1) * 8;

    #pragma unroll 1
    for (int nh = 0; nh < 2; nh++) {
        const int nbase = nh * 256;

        float acc2[2][8][4];
        #pragma unroll
        for (int mt = 0; mt < 2; mt++)
            #pragma unroll
            for (int nb = 0; nb < 8; nb++)
                #pragma unroll
                for (int q = 0; q < 4; q++)
                    acc2[mt][nb][q] = 0.0f;

        stage_b(sb, 0, 0, nbase, tid);
        stage_b(sb, 1, 1, nbase, tid);

        #pragma unroll 1
        for (int kt = 0; kt < NKT2; kt++) {
            if (kt < NKT2 - 1) cp_wait<1>(); else cp_wait<0>();
            __syncthreads();

            const uint32_t bbuf = sb + BSTG_OFF(kt & 1);

            #pragma unroll
            for (int kk = 0; kk < 4; kk++) {
                uint32_t ah[2][4];
                #pragma unroll
                for (int mt = 0; mt < 2; mt++) {
                    uint32_t aoff = (uint32_t)((wm * 32 + mt * 16 + a_row) * HS_B
                                               + (kt * 64 + kk * 16 + a_kof) * 2);
                    ldsm_x4(sb + HS_OFF + aoff, ah[mt]);
                }
                #pragma unroll
                for (int nb4 = 0; nb4 < 4; nb4++) {
                    uint32_t bh[4];
                    uint32_t boff = (uint32_t)((wn * 64 + nb4 * 16 + b_row) * BSTG_B
                                               + (kk * 16 + b_kof) * 2);
                    ldsm_x4(bbuf + boff, bh);
                    #pragma unroll
                    for (int mt = 0; mt < 2; mt++) {
                        #pragma unroll
                        for (int s = 0; s < 2; s++) {
                            mma_f16(acc2[mt][nb4 * 2 + s], ah[mt], &bh[s * 2]);
                        }
                    }
                }
            }
            __syncthreads();

            if (kt + 2 < NKT2)
                stage_b(sb, kt & 1, kt + 2, nbase, tid);
        }

        // epilogue: add b2, store this N-half
        #pragma unroll
        for (int mt = 0; mt < 2; mt++) {
            const int r0 = e0 + wm * 32 + mt * 16 + (lane >> 2);
            const int r1 = r0 + 8;
            #pragma unroll
            for (int nb = 0; nb < 8; nb++) {
                const int col = nbase + wn * 64 + nb * 8 + (lane & 3) * 2;
                float2 bb = *(const float2*)&b2[col];
                if (r0 < E) {
                    float2 v0;
                    v0.x = acc2[mt][nb][0] + bb.x;
                    v0.y = acc2[mt][nb][1] + bb.y;
                    *(float2*)&out[(size_t)r0 * OUTF + col] = v0;
                }
                if (r1 < E) {
                    float2 v1;
                    v1.x = acc2[mt][nb][2] + bb.x;
                    v1.y = acc2[mt][nb][3] + bb.y;
                    *(float2*)&out[(size_t)r1 * OUTF + col] = v1;
                }
            }
        }
        // trailing __syncthreads of kt-loop already ran; B bufs of next half are
        // staged only after all warps passed that barrier on entry to next nh's
        // first cp_wait+sync, so no extra barrier needed here.
    }
}

// ============================= launch =============================
extern "C" void kernel_launch(void* const* d_in, const int* in_sizes, int n_in,
                              void* d_out, int out_size) {
    const float* src       = (const float*)d_in[0];
    const float* dest      = (const float*)d_in[1];
    const float* edge_attr = (const float*)d_in[2];
    const float* u         = (const float*)d_in[3];
    const int*   batch     = (const int*)d_in[4];     // int32 (JAX default)
    const float* W1        = (const float*)d_in[5];
    const float* b1        = (const float*)d_in[6];
    const float* W2        = (const float*)d_in[7];
    const float* b2        = (const float*)d_in[8];
    float*       out       = (float*)d_out;

    const int E        = in_sizes[0] / NODE_F;
    const int n_graphs = in_sizes[3] / U_F;

    static int configured = 0;
    if (!configured) {
        cudaFuncSetAttribute(edge_mlp_fused,
                             cudaFuncAttributeMaxDynamicSharedMemorySize, SMEM_TOTAL);
        configured = 1;
    }

    prep_w2<<<(HDIM * OUTF + 255) / 256, 256>>>(W2);

    edge_mlp_fused<<<(E + BM - 1) / BM, NT, SMEM_TOTAL>>>(
        src, dest, edge_attr, u, batch, W1, b1, b2, out, E, n_graphs);
}